// round 6
// baseline (speedup 1.0000x reference)
#include <cuda_runtime.h>

#define NN 100000
#define EE 1600000
#define BB 1024
#define SCAN_B 98   // ceil(NN/1024)

// ---------------- scratch (device globals) -----------------------------------
__device__ __align__(128) float d_h   [NN * 128];
__device__ __align__(128) float d_as  [NN * 4];
__device__ __align__(128) float d_ad  [NN * 4];
__device__ __align__(128) float d_gat [NN * 128];
__device__ __align__(128) float d_h1  [NN * 64];
__device__ __align__(128) float d_o2  [NN * 64];
__device__ __align__(128) float d_h2  [NN * 128];
__device__ __align__(128) float d_dinv[NN];
__device__ __align__(128) float d_pool[BB * 128];
__device__ __align__(128) float d_cnt [BB];
__device__ __align__(128) float d_s1  [BB * 64 * 18];
__device__ __align__(128) float d_s2  [BB * 64 * 16];
__device__ __align__(128) float d_fc  [BB * 64];
__device__ __align__(128) int   d_degi[NN];
__device__ __align__(128) int   d_off [NN];
__device__ __align__(128) int   d_cur [NN];
__device__ __align__(128) int   d_csr [EE];
__device__ __align__(128) int   d_bsum [SCAN_B];
__device__ __align__(128) int   d_bbase[SCAN_B];

__device__ __forceinline__ float lrelu(float x, float s) { return x < 0.f ? s * x : x; }

__device__ __forceinline__ void redAdd4(float* p, float a, float b, float c, float d) {
    asm volatile("red.global.add.v4.f32 [%0], {%1,%2,%3,%4};"
                 :: "l"(p), "f"(a), "f"(b), "f"(c), "f"(d) : "memory");
}

// ---------------- init --------------------------------------------------------
__global__ void k_init() {
    int i = blockIdx.x * 256 + threadIdx.x;
    if (i < NN)       d_degi[i] = 0;
    if (i < BB * 128) d_pool[i] = 0.f;
    if (i < BB)       d_cnt[i]  = 0.f;
}

// ---------------- node transform ----------------------------------------------
__global__ void k_node(const float* __restrict__ x, const float* __restrict__ Wg,
                       const float* __restrict__ atts, const float* __restrict__ attd) {
    int idx = blockIdx.x * 256 + threadIdx.x;      // NN*128 threads
    int node = idx >> 7, f = idx & 127;
    float acc = 0.f;
    #pragma unroll
    for (int k = 0; k < 9; k++) acc += x[node * 9 + k] * Wg[k * 128 + f];
    d_h[idx] = acc;
    int head = f >> 5, c = f & 31;
    float ts = acc * atts[head * 32 + c];
    float td = acc * attd[head * 32 + c];
    #pragma unroll
    for (int off = 16; off > 0; off >>= 1) {
        ts += __shfl_xor_sync(0xffffffffu, ts, off);
        td += __shfl_xor_sync(0xffffffffu, td, off);
    }
    if ((threadIdx.x & 31) == 0) {
        d_as[node * 4 + head] = ts;
        d_ad[node * 4 + head] = td;
    }
}

// ---------------- degree histogram + batch counts ------------------------------
__global__ void k_hist(const int* __restrict__ ei, const int* __restrict__ batch) {
    int idx = blockIdx.x * 256 + threadIdx.x;
    if (idx < EE) atomicAdd(&d_degi[ei[EE + idx]], 1);
    if (idx < NN) atomicAdd(&d_cnt[batch[idx]], 1.0f);
}

// ---------------- scan ---------------------------------------------------------
__global__ void k_scanA() {
    __shared__ int sm[1024];
    int i = blockIdx.x * 1024 + threadIdx.x;
    int v = (i < NN) ? d_degi[i] : 0;
    sm[threadIdx.x] = v;
    __syncthreads();
    for (int off = 1; off < 1024; off <<= 1) {
        int t = (threadIdx.x >= off) ? sm[threadIdx.x - off] : 0;
        __syncthreads();
        sm[threadIdx.x] += t;
        __syncthreads();
    }
    if (i < NN) d_off[i] = sm[threadIdx.x] - v;
    if (threadIdx.x == 1023) d_bsum[blockIdx.x] = sm[1023];
}

__global__ void k_scanB() {
    __shared__ int sm[128];
    int t = threadIdx.x;
    int v = (t < SCAN_B) ? d_bsum[t] : 0;
    sm[t] = v;
    __syncthreads();
    for (int off = 1; off < 128; off <<= 1) {
        int tv = (t >= off) ? sm[t - off] : 0;
        __syncthreads();
        sm[t] += tv;
        __syncthreads();
    }
    if (t < SCAN_B) d_bbase[t] = sm[t] - v;   // exclusive
}

__global__ void k_scanC() {
    int i = blockIdx.x * 1024 + threadIdx.x;
    if (i < NN) {
        int o = d_off[i] + d_bbase[blockIdx.x];
        d_off[i] = o;
        d_cur[i] = o;
        d_dinv[i] = rsqrtf((float)(d_degi[i] + 1));
    }
}

// ---------------- CSR fill ------------------------------------------------------
__global__ void k_fill(const int* __restrict__ ei) {
    int idx = blockIdx.x * 256 + threadIdx.x;
    if (idx < EE) {
        int dst = ei[EE + idx];
        int p = atomicAdd(&d_cur[dst], 1);
        d_csr[p] = ei[idx];
    }
}

// ---------------- fused GAT: online-softmax gather (warp per dst node) --------
// (byte-identical to the R2 1001us version)
__global__ void k_gat(const float* __restrict__ bg) {
    int gw = (blockIdx.x * 256 + threadIdx.x) >> 5;   // node id
    if (gw >= NN) return;
    int lane = threadIdx.x & 31;
    int h = lane >> 3;                                 // head (4 heads x 8 lanes)
    int d = gw;

    float add_ = d_ad[d * 4 + h];
    // self loop seeds the online softmax
    float m = lrelu(d_as[d * 4 + h] + add_, 0.2f);
    float s = 1.0f;
    float4 acc = *(const float4*)&d_h[d * 128 + lane * 4];

    int start = d_off[d];
    int cntE  = d_degi[d];
    for (int p0 = 0; p0 < cntE; p0 += 32) {
        int src_l = (p0 + lane < cntE) ? d_csr[start + p0 + lane] : 0;
        int lim = min(32, cntE - p0);
        for (int j = 0; j < lim; j++) {
            int src = __shfl_sync(0xffffffffu, src_l, j);
            float e = lrelu(d_as[src * 4 + h] + add_, 0.2f);
            float4 hv = *(const float4*)&d_h[src * 128 + lane * 4];
            if (e <= m) {
                float w = __expf(e - m);
                s += w;
                acc.x += hv.x * w; acc.y += hv.y * w;
                acc.z += hv.z * w; acc.w += hv.w * w;
            } else {
                float r = __expf(m - e);
                s = s * r + 1.0f;
                acc.x = acc.x * r + hv.x; acc.y = acc.y * r + hv.y;
                acc.z = acc.z * r + hv.z; acc.w = acc.w * r + hv.w;
                m = e;
            }
        }
    }
    float inv = 1.0f / (s + 1e-16f);
    float4 bb = *(const float4*)&bg[lane * 4];
    float4 o;
    o.x = lrelu(acc.x * inv + bb.x, 0.01f);
    o.y = lrelu(acc.y * inv + bb.y, 0.01f);
    o.z = lrelu(acc.z * inv + bb.z, 0.01f);
    o.w = lrelu(acc.w * inv + bb.w, 0.01f);
    *(float4*)&d_gat[d * 128 + lane * 4] = o;
}

// ---------------- GEMM1: h1 = d_gat @ W2 (128 -> 64), 2 nodes/thread ----------
__global__ void k_gemm1(const float* __restrict__ W2) {
    __shared__ float Ws[128 * 64];                 // [k][o] conflict-free
    for (int i = threadIdx.x; i < 128 * 64; i += 256) Ws[i] = W2[i];
    __syncthreads();
    int o = threadIdx.x & 63, nl = threadIdx.x >> 6;   // nl in 0..3
    for (int n0 = blockIdx.x * 8; n0 < NN; n0 += gridDim.x * 8) {
        int na = n0 + nl * 2;                          // NN % 8 == 0 -> no tail
        int nb = na + 1;
        const float4* ga = (const float4*)&d_gat[na * 128];
        const float4* gb = (const float4*)&d_gat[nb * 128];
        float a0 = 0.f, a1 = 0.f;
        #pragma unroll
        for (int kk = 0; kk < 32; kk++) {
            float4 va = ga[kk];
            float4 vb = gb[kk];
            float w0 = Ws[(kk * 4 + 0) * 64 + o];
            float w1 = Ws[(kk * 4 + 1) * 64 + o];
            float w2 = Ws[(kk * 4 + 2) * 64 + o];
            float w3 = Ws[(kk * 4 + 3) * 64 + o];
            a0 += va.x * w0 + va.y * w1 + va.z * w2 + va.w * w3;
            a1 += vb.x * w0 + vb.y * w1 + vb.z * w2 + vb.w * w3;
        }
        d_h1[na * 64 + o] = a0;
        d_h1[nb * 64 + o] = a1;
    }
}

// ---------------- GCN1 gather (warp per node) — identical to R2 ---------------
__global__ void k_gcn1(const float* __restrict__ b2) {
    int gw = (blockIdx.x * 256 + threadIdx.x) >> 5;
    if (gw >= NN) return;
    int lane = threadIdx.x & 31;
    int d = gw;
    float did = d_dinv[d];

    float2 hv = *(const float2*)&d_h1[d * 64 + lane * 2];
    float2 acc; acc.x = hv.x * did; acc.y = hv.y * did;

    int start = d_off[d];
    int cntE  = d_degi[d];
    for (int p0 = 0; p0 < cntE; p0 += 32) {
        int   src_l = 0;
        float dv_l  = 0.f;
        if (p0 + lane < cntE) { src_l = d_csr[start + p0 + lane]; dv_l = d_dinv[src_l]; }
        int lim = min(32, cntE - p0);
        for (int j = 0; j < lim; j++) {
            int   src = __shfl_sync(0xffffffffu, src_l, j);
            float dv  = __shfl_sync(0xffffffffu, dv_l, j);
            float2 v = *(const float2*)&d_h1[src * 64 + lane * 2];
            acc.x += v.x * dv; acc.y += v.y * dv;
        }
    }
    float2 o;
    o.x = lrelu(acc.x * did + b2[lane * 2 + 0], 0.01f);
    o.y = lrelu(acc.y * did + b2[lane * 2 + 1], 0.01f);
    *(float2*)&d_o2[d * 64 + lane * 2] = o;
}

// ---------------- GEMM2: h2 = d_o2 @ W3 (64 -> 128), 2 nodes/thread ----------
__global__ void k_gemm2(const float* __restrict__ W3) {
    __shared__ float Ws[64 * 128];                 // [k][o] conflict-free
    for (int i = threadIdx.x; i < 64 * 128; i += 256) Ws[i] = W3[i];
    __syncthreads();
    int o = threadIdx.x & 127, nl = threadIdx.x >> 7;  // nl in 0..1
    for (int n0 = blockIdx.x * 4; n0 < NN; n0 += gridDim.x * 4) {
        int na = n0 + nl * 2;                          // NN % 4 == 0 -> no tail
        int nb = na + 1;
        const float4* ga = (const float4*)&d_o2[na * 64];
        const float4* gb = (const float4*)&d_o2[nb * 64];
        float a0 = 0.f, a1 = 0.f;
        #pragma unroll
        for (int kk = 0; kk < 16; kk++) {
            float4 va = ga[kk];
            float4 vb = gb[kk];
            float w0 = Ws[(kk * 4 + 0) * 128 + o];
            float w1 = Ws[(kk * 4 + 1) * 128 + o];
            float w2 = Ws[(kk * 4 + 2) * 128 + o];
            float w3 = Ws[(kk * 4 + 3) * 128 + o];
            a0 += va.x * w0 + va.y * w1 + va.z * w2 + va.w * w3;
            a1 += vb.x * w0 + vb.y * w1 + vb.z * w2 + vb.w * w3;
        }
        d_h2[na * 128 + o] = a0;
        d_h2[nb * 128 + o] = a1;
    }
}

// ---------------- GCN2 gather + fused pool — identical to R2 ------------------
__global__ void k_gcn2pool(const float* __restrict__ b3, const int* __restrict__ batch) {
    int gw = (blockIdx.x * 256 + threadIdx.x) >> 5;
    if (gw >= NN) return;
    int lane = threadIdx.x & 31;
    int d = gw;
    float did = d_dinv[d];

    float4 hv = *(const float4*)&d_h2[d * 128 + lane * 4];
    float4 acc; acc.x = hv.x * did; acc.y = hv.y * did; acc.z = hv.z * did; acc.w = hv.w * did;

    int start = d_off[d];
    int cntE  = d_degi[d];
    for (int p0 = 0; p0 < cntE; p0 += 32) {
        int   src_l = 0;
        float dv_l  = 0.f;
        if (p0 + lane < cntE) { src_l = d_csr[start + p0 + lane]; dv_l = d_dinv[src_l]; }
        int lim = min(32, cntE - p0);
        for (int j = 0; j < lim; j++) {
            int   src = __shfl_sync(0xffffffffu, src_l, j);
            float dv  = __shfl_sync(0xffffffffu, dv_l, j);
            float4 v = *(const float4*)&d_h2[src * 128 + lane * 4];
            acc.x += v.x * dv; acc.y += v.y * dv; acc.z += v.z * dv; acc.w += v.w * dv;
        }
    }
    float4 bb = *(const float4*)&b3[lane * 4];
    float ox = lrelu(acc.x * did + bb.x, 0.01f);
    float oy = lrelu(acc.y * did + bb.y, 0.01f);
    float oz = lrelu(acc.z * did + bb.z, 0.01f);
    float ow = lrelu(acc.w * did + bb.w, 0.01f);
    int b = batch[d];
    redAdd4(&d_pool[b * 128 + lane * 4], ox, oy, oz, ow);
}

// ---------------- sequence branch ---------------------------------------------
__global__ void k_seq1(const float* __restrict__ seq, const float* __restrict__ w,
                       const float* __restrict__ bias,
                       const float* __restrict__ g, const float* __restrict__ be,
                       const float* __restrict__ m, const float* __restrict__ v) {
    int idx = blockIdx.x * 256 + threadIdx.x;       // BB*64*18
    int b = idx / 1152, r = idx % 1152, co = r / 18, t = r % 18;
    float acc = bias[co];
    #pragma unroll 5
    for (int ci = 0; ci < 30; ci++) {
        const float* sp = &seq[b * 600 + ci * 20 + t];
        const float* wp = &w[(co * 30 + ci) * 3];
        acc += sp[0] * wp[0] + sp[1] * wp[1] + sp[2] * wp[2];
    }
    acc = (acc - m[co]) * rsqrtf(v[co] + 1e-5f) * g[co] + be[co];
    d_s1[idx] = lrelu(acc, 0.01f);
}

__global__ void k_seq2(const float* __restrict__ w, const float* __restrict__ bias,
                       const float* __restrict__ g, const float* __restrict__ be,
                       const float* __restrict__ m, const float* __restrict__ v) {
    int idx = blockIdx.x * 256 + threadIdx.x;       // BB*64*16
    int b = idx >> 10, r = idx & 1023, co = r >> 4, t = r & 15;
    float acc = bias[co];
    #pragma unroll 8
    for (int ci = 0; ci < 64; ci++) {
        const float* sp = &d_s1[b * 1152 + ci * 18 + t];
        const float* wp = &w[(co * 64 + ci) * 3];
        acc += sp[0] * wp[0] + sp[1] * wp[1] + sp[2] * wp[2];
    }
    acc = (acc - m[co]) * rsqrtf(v[co] + 1e-5f) * g[co] + be[co];
    d_s2[idx] = lrelu(acc, 0.01f);
}

__global__ void k_fc1(const float* __restrict__ W, const float* __restrict__ bias) {
    int tid = threadIdx.x;                          // grid 64 x 256
    int o = tid & 63, q = tid >> 6;
    int b0 = blockIdx.x * 16 + q * 4;
    float a0 = bias[o], a1 = a0, a2 = a0, a3 = a0;
    #pragma unroll 4
    for (int k = 0; k < 1024; k++) {
        float ww = W[k * 64 + o];
        a0 += d_s2[(b0 + 0) * 1024 + k] * ww;
        a1 += d_s2[(b0 + 1) * 1024 + k] * ww;
        a2 += d_s2[(b0 + 2) * 1024 + k] * ww;
        a3 += d_s2[(b0 + 3) * 1024 + k] * ww;
    }
    d_fc[(b0 + 0) * 64 + o] = a0;
    d_fc[(b0 + 1) * 64 + o] = a1;
    d_fc[(b0 + 2) * 64 + o] = a2;
    d_fc[(b0 + 3) * 64 + o] = a3;
}

// ---------------- fusion + classifier head ------------------------------------
__global__ void k_head(const float* __restrict__ fusW, const float* __restrict__ fusb,
                       const float* __restrict__ c1W, const float* __restrict__ c1b,
                       const float* __restrict__ c3W, const float* __restrict__ c3b,
                       float* __restrict__ out) {
    __shared__ float comb[192], t1[128], t2[64];
    int b = blockIdx.x, tid = threadIdx.x;          // 128 threads
    if (tid < 128) comb[tid] = d_pool[b * 128 + tid] / fmaxf(d_cnt[b], 1.0f);
    if (tid < 64)  comb[128 + tid] = d_fc[b * 64 + tid];
    __syncthreads();
    float acc = fusb[tid];
    #pragma unroll 8
    for (int k = 0; k < 192; k++) acc += comb[k] * fusW[k * 128 + tid];
    t1[tid] = lrelu(acc, 0.01f);
    __syncthreads();
    if (tid < 64) {
        float a = c1b[tid];
        #pragma unroll 8
        for (int k = 0; k < 128; k++) a += t1[k] * c1W[k * 64 + tid];
        t2[tid] = lrelu(a, 0.01f);
    }
    __syncthreads();
    if (tid == 0) {
        float a = c3b[0];
        #pragma unroll 8
        for (int k = 0; k < 64; k++) a += t2[k] * c3W[k];
        out[b] = a;
    }
}

// ---------------- launch ------------------------------------------------------
extern "C" void kernel_launch(void* const* d_in, const int* in_sizes, int n_in,
                              void* d_out, int out_size) {
    const float* x     = (const float*)d_in[0];
    const int*   ei    = (const int*)  d_in[1];
    const int*   batch = (const int*)  d_in[2];
    const float* seq   = (const float*)d_in[3];
    const float* Wg    = (const float*)d_in[4];
    const float* atts  = (const float*)d_in[5];
    const float* attd  = (const float*)d_in[6];
    const float* bg    = (const float*)d_in[7];
    const float* W2    = (const float*)d_in[8];
    const float* b2    = (const float*)d_in[9];
    const float* W3    = (const float*)d_in[10];
    const float* b3    = (const float*)d_in[11];
    const float* c1w   = (const float*)d_in[12];
    const float* c1bv  = (const float*)d_in[13];
    const float* c2w   = (const float*)d_in[14];
    const float* c2bv  = (const float*)d_in[15];
    const float* bn1g  = (const float*)d_in[16];
    const float* bn1b  = (const float*)d_in[17];
    const float* bn1m  = (const float*)d_in[18];
    const float* bn1v  = (const float*)d_in[19];
    const float* bn2g  = (const float*)d_in[20];
    const float* bn2b  = (const float*)d_in[21];
    const float* bn2m  = (const float*)d_in[22];
    const float* bn2v  = (const float*)d_in[23];
    const float* fcW   = (const float*)d_in[24];
    const float* fcb   = (const float*)d_in[25];
    const float* fusW  = (const float*)d_in[26];
    const float* fusb  = (const float*)d_in[27];
    const float* cls1W = (const float*)d_in[28];
    const float* cls1b = (const float*)d_in[29];
    const float* cls3W = (const float*)d_in[30];
    const float* cls3b = (const float*)d_in[31];
    float* out = (float*)d_out;

    k_init  <<<512, 256>>>();
    k_node  <<<50000, 256>>>(x, Wg, atts, attd);
    k_hist  <<<(EE + 255) / 256, 256>>>(ei, batch);
    k_scanA <<<SCAN_B, 1024>>>();
    k_scanB <<<1, 128>>>();
    k_scanC <<<SCAN_B, 1024>>>();
    k_fill  <<<(EE + 255) / 256, 256>>>(ei);
    k_gat   <<<12500, 256>>>(bg);
    k_gemm1 <<<1184, 256>>>(W2);
    k_gcn1  <<<12500, 256>>>(b2);
    k_gemm2 <<<1184, 256>>>(W3);
    k_gcn2pool<<<12500, 256>>>(b3, batch);
    k_seq1  <<<BB * 1152 / 256, 256>>>(seq, c1w, c1bv, bn1g, bn1b, bn1m, bn1v);
    k_seq2  <<<BB * 1024 / 256, 256>>>(c2w, c2bv, bn2g, bn2b, bn2m, bn2v);
    k_fc1   <<<64, 256>>>(fcW, fcb);
    k_head  <<<BB, 128>>>(fusW, fusb, cls1W, cls1b, cls3W, cls3b, out);
}

// round 7
// speedup vs baseline: 1.1687x; 1.1687x over previous
#include <cuda_runtime.h>

#define NN 100000
#define EE 1600000
#define BB 1024
#define SCAN_B 98   // ceil(NN/1024)

// ---------------- scratch (device globals) -----------------------------------
__device__ __align__(128) float d_x12 [NN * 12];   // x padded to 12 floats/row
__device__ __align__(128) float d_as  [NN * 4];
__device__ __align__(128) float d_ad  [NN * 4];
__device__ __align__(128) float d_gat [NN * 128];
__device__ __align__(128) float d_h1  [NN * 64];
__device__ __align__(128) float d_o2  [NN * 64];
__device__ __align__(128) float d_ag2 [NN * 64];   // aggregated o2 (pre-GEMM2)
__device__ __align__(128) float d_dinv[NN];
__device__ __align__(128) float d_pool[BB * 128];
__device__ __align__(128) float d_cnt [BB];
__device__ __align__(128) float d_s1  [BB * 64 * 18];
__device__ __align__(128) float d_s2  [BB * 64 * 16];
__device__ __align__(128) float d_fc  [BB * 64];
__device__ __align__(128) float d_vs  [36];        // per-head src attn vectors (4x9)
__device__ __align__(128) float d_vd  [36];
__device__ __align__(128) int   d_degi[NN];
__device__ __align__(128) int   d_off [NN];
__device__ __align__(128) int   d_cur [NN];
__device__ __align__(128) int   d_csr [EE];
__device__ __align__(128) int   d_bsum [SCAN_B];
__device__ __align__(128) int   d_bbase[SCAN_B];

__device__ __forceinline__ float lrelu(float x, float s) { return x < 0.f ? s * x : x; }

__device__ __forceinline__ void redAdd4(float* p, float a, float b, float c, float d) {
    asm volatile("red.global.add.v4.f32 [%0], {%1,%2,%3,%4};"
                 :: "l"(p), "f"(a), "f"(b), "f"(c), "f"(d) : "memory");
}

// ---------------- init --------------------------------------------------------
__global__ void k_init() {
    int i = blockIdx.x * 256 + threadIdx.x;
    if (i < NN)       d_degi[i] = 0;
    if (i < BB * 128) d_pool[i] = 0.f;
    if (i < BB)       d_cnt[i]  = 0.f;
}

// ---------------- attention projection vectors: vs/vd = Wg @ att --------------
__global__ void k_att(const float* __restrict__ Wg, const float* __restrict__ atts,
                      const float* __restrict__ attd) {
    int t = threadIdx.x;
    if (t < 36) {
        int h = t / 9, k = t % 9;
        float s = 0.f, d = 0.f;
        #pragma unroll
        for (int c = 0; c < 32; c++) {
            float w = Wg[k * 128 + h * 32 + c];
            s += w * atts[h * 32 + c];
            d += w * attd[h * 32 + c];
        }
        d_vs[t] = s;
        d_vd[t] = d;
    }
}

// ---------------- per-node attn logits + padded x -----------------------------
__global__ void k_node2(const float* __restrict__ x) {
    int n = blockIdx.x * 256 + threadIdx.x;
    if (n >= NN) return;
    float xv[9];
    #pragma unroll
    for (int k = 0; k < 9; k++) xv[k] = x[n * 9 + k];
    #pragma unroll
    for (int k = 0; k < 9; k++) d_x12[n * 12 + k] = xv[k];
    #pragma unroll
    for (int k = 9; k < 12; k++) d_x12[n * 12 + k] = 0.f;
    #pragma unroll
    for (int h = 0; h < 4; h++) {
        float as = 0.f, ad = 0.f;
        #pragma unroll
        for (int k = 0; k < 9; k++) {
            as += xv[k] * d_vs[h * 9 + k];
            ad += xv[k] * d_vd[h * 9 + k];
        }
        d_as[n * 4 + h] = as;
        d_ad[n * 4 + h] = ad;
    }
}

// ---------------- degree histogram + batch counts ------------------------------
__global__ void k_hist(const int* __restrict__ ei, const int* __restrict__ batch) {
    int idx = blockIdx.x * 256 + threadIdx.x;
    if (idx < EE) atomicAdd(&d_degi[ei[EE + idx]], 1);
    if (idx < NN) atomicAdd(&d_cnt[batch[idx]], 1.0f);
}

// ---------------- scan ---------------------------------------------------------
__global__ void k_scanA() {
    __shared__ int sm[1024];
    int i = blockIdx.x * 1024 + threadIdx.x;
    int v = (i < NN) ? d_degi[i] : 0;
    sm[threadIdx.x] = v;
    __syncthreads();
    for (int off = 1; off < 1024; off <<= 1) {
        int t = (threadIdx.x >= off) ? sm[threadIdx.x - off] : 0;
        __syncthreads();
        sm[threadIdx.x] += t;
        __syncthreads();
    }
    if (i < NN) d_off[i] = sm[threadIdx.x] - v;
    if (threadIdx.x == 1023) d_bsum[blockIdx.x] = sm[1023];
}

__global__ void k_scanB() {
    __shared__ int sm[128];
    int t = threadIdx.x;
    int v = (t < SCAN_B) ? d_bsum[t] : 0;
    sm[t] = v;
    __syncthreads();
    for (int off = 1; off < 128; off <<= 1) {
        int tv = (t >= off) ? sm[t - off] : 0;
        __syncthreads();
        sm[t] += tv;
        __syncthreads();
    }
    if (t < SCAN_B) d_bbase[t] = sm[t] - v;   // exclusive
}

__global__ void k_scanC() {
    int i = blockIdx.x * 1024 + threadIdx.x;
    if (i < NN) {
        int o = d_off[i] + d_bbase[blockIdx.x];
        d_off[i] = o;
        d_cur[i] = o;
        d_dinv[i] = rsqrtf((float)(d_degi[i] + 1));
    }
}

// ---------------- CSR fill ------------------------------------------------------
__global__ void k_fill(const int* __restrict__ ei) {
    int idx = blockIdx.x * 256 + threadIdx.x;
    if (idx < EE) {
        int dst = ei[EE + idx];
        int p = atomicAdd(&d_cur[dst], 1);
        d_csr[p] = ei[idx];
    }
}

// ---------------- fused GAT on hoisted x: warp/node, lane=(slot,head) ---------
// out = (softmax-weighted sum of x_src) @ Wg + bias, exploiting linearity.
__global__ void k_gat(const float* __restrict__ Wg, const float* __restrict__ bg) {
    __shared__ float sm_ax[8][4][10];
    int wb = threadIdx.x >> 5;
    int node = blockIdx.x * 8 + wb;
    if (node >= NN) return;
    int lane = threadIdx.x & 31;
    int g = lane >> 2;          // neighbor slot 0..7
    int h = lane & 3;           // head

    float add_ = d_ad[node * 4 + h];
    float m = -1e30f, s = 0.f;
    float ax[12];
    #pragma unroll
    for (int k = 0; k < 12; k++) ax[k] = 0.f;

    int start = d_off[node], cnt = d_degi[node];
    for (int p0 = 0; p0 < cnt; p0 += 8) {
        int idx = p0 + g;
        if (idx < cnt) {
            int src = d_csr[start + idx];
            float e = lrelu(d_as[src * 4 + h] + add_, 0.2f);
            float nm = fmaxf(m, e);
            float r = __expf(m - nm);
            float w = __expf(e - nm);
            s = s * r + w;
            const float4* xr = (const float4*)&d_x12[src * 12];
            float4 x0 = xr[0], x1 = xr[1], x2 = xr[2];
            ax[0] = ax[0] * r + w * x0.x;  ax[1] = ax[1] * r + w * x0.y;
            ax[2] = ax[2] * r + w * x0.z;  ax[3] = ax[3] * r + w * x0.w;
            ax[4] = ax[4] * r + w * x1.x;  ax[5] = ax[5] * r + w * x1.y;
            ax[6] = ax[6] * r + w * x1.z;  ax[7] = ax[7] * r + w * x1.w;
            ax[8] = ax[8] * r + w * x2.x;
            m = nm;
        }
    }
    // butterfly merge across neighbor-slot dimension (strides 4, 8, 16)
    #pragma unroll
    for (int off = 4; off < 32; off <<= 1) {
        float m2 = __shfl_xor_sync(0xffffffffu, m, off);
        float s2 = __shfl_xor_sync(0xffffffffu, s, off);
        float nm = fmaxf(m, m2);
        float r1 = __expf(m - nm);
        float r2 = __expf(m2 - nm);
        s = s * r1 + s2 * r2;
        #pragma unroll
        for (int k = 0; k < 9; k++) {
            float a2 = __shfl_xor_sync(0xffffffffu, ax[k], off);
            ax[k] = ax[k] * r1 + a2 * r2;
        }
        m = nm;
    }
    // fold self loop, normalize, stage per-head aggregates (lanes 0..3: h==lane)
    if (lane < 4) {
        float es = lrelu(d_as[node * 4 + lane] + add_, 0.2f);
        float nm = fmaxf(m, es);
        float r = __expf(m - nm);
        float wse = __expf(es - nm);
        float st = s * r + wse;
        float inv = 1.f / (st + 1e-16f);
        #pragma unroll
        for (int k = 0; k < 9; k++)
            sm_ax[wb][lane][k] = (ax[k] * r + wse * d_x12[node * 12 + k]) * inv;
    }
    __syncwarp();
    // projection: out[f] = sum_k aggx[head(f)][k] * Wg[k,f] + bg[f]
    int hh = lane >> 3;
    float a[9];
    #pragma unroll
    for (int k = 0; k < 9; k++) a[k] = sm_ax[wb][hh][k];
    float4 o = *(const float4*)&bg[lane * 4];
    #pragma unroll
    for (int k = 0; k < 9; k++) {
        float4 wr = *(const float4*)&Wg[k * 128 + lane * 4];
        o.x += a[k] * wr.x; o.y += a[k] * wr.y;
        o.z += a[k] * wr.z; o.w += a[k] * wr.w;
    }
    o.x = lrelu(o.x, 0.01f); o.y = lrelu(o.y, 0.01f);
    o.z = lrelu(o.z, 0.01f); o.w = lrelu(o.w, 0.01f);
    *(float4*)&d_gat[node * 128 + lane * 4] = o;
}

// ---------------- GEMM1: h1 = d_gat @ W2 (128 -> 64), float4 LDS --------------
__global__ void k_gemm1(const float* __restrict__ W2) {
    __shared__ float Ws[128 * 64];                 // [k][o]
    for (int i = threadIdx.x; i < 128 * 64; i += 256) Ws[i] = W2[i];
    __syncthreads();
    int q = threadIdx.x & 15;                      // output quad (64 outputs)
    int nl = threadIdx.x >> 4;                     // 16 nodes per block-iter
    for (int n0 = blockIdx.x * 16; n0 < NN; n0 += gridDim.x * 16) {
        int node = n0 + nl;                        // NN % 16 == 0
        const float4* g4 = (const float4*)&d_gat[node * 128];
        float4 acc = make_float4(0.f, 0.f, 0.f, 0.f);
        #pragma unroll
        for (int kk = 0; kk < 32; kk++) {
            float4 gv = g4[kk];
            float4 w0 = *(const float4*)&Ws[(kk * 4 + 0) * 64 + q * 4];
            float4 w1 = *(const float4*)&Ws[(kk * 4 + 1) * 64 + q * 4];
            float4 w2 = *(const float4*)&Ws[(kk * 4 + 2) * 64 + q * 4];
            float4 w3 = *(const float4*)&Ws[(kk * 4 + 3) * 64 + q * 4];
            acc.x += gv.x * w0.x + gv.y * w1.x + gv.z * w2.x + gv.w * w3.x;
            acc.y += gv.x * w0.y + gv.y * w1.y + gv.z * w2.y + gv.w * w3.y;
            acc.z += gv.x * w0.z + gv.y * w1.z + gv.z * w2.z + gv.w * w3.z;
            acc.w += gv.x * w0.w + gv.y * w1.w + gv.z * w2.w + gv.w * w3.w;
        }
        *(float4*)&d_h1[node * 64 + q * 4] = acc;
    }
}

// ---------------- GCN1 gather (warp per node) — R2 structure ------------------
__global__ void k_gcn1(const float* __restrict__ b2) {
    int gw = (blockIdx.x * 256 + threadIdx.x) >> 5;
    if (gw >= NN) return;
    int lane = threadIdx.x & 31;
    int d = gw;
    float did = d_dinv[d];

    float2 hv = *(const float2*)&d_h1[d * 64 + lane * 2];
    float2 acc; acc.x = hv.x * did; acc.y = hv.y * did;

    int start = d_off[d];
    int cntE  = d_degi[d];
    for (int p0 = 0; p0 < cntE; p0 += 32) {
        int   src_l = 0;
        float dv_l  = 0.f;
        if (p0 + lane < cntE) { src_l = d_csr[start + p0 + lane]; dv_l = d_dinv[src_l]; }
        int lim = min(32, cntE - p0);
        for (int j = 0; j < lim; j++) {
            int   src = __shfl_sync(0xffffffffu, src_l, j);
            float dv  = __shfl_sync(0xffffffffu, dv_l, j);
            float2 v = *(const float2*)&d_h1[src * 64 + lane * 2];
            acc.x += v.x * dv; acc.y += v.y * dv;
        }
    }
    float2 o;
    o.x = lrelu(acc.x * did + b2[lane * 2 + 0], 0.01f);
    o.y = lrelu(acc.y * did + b2[lane * 2 + 1], 0.01f);
    *(float2*)&d_o2[d * 64 + lane * 2] = o;
}

// ---------------- GCN2 aggregation on o2 (64-wide; GEMM hoisted after) --------
__global__ void k_gcn2agg() {
    int gw = (blockIdx.x * 256 + threadIdx.x) >> 5;
    if (gw >= NN) return;
    int lane = threadIdx.x & 31;
    int d = gw;
    float did = d_dinv[d];

    float2 hv = *(const float2*)&d_o2[d * 64 + lane * 2];
    float2 acc; acc.x = hv.x * did; acc.y = hv.y * did;

    int start = d_off[d];
    int cntE  = d_degi[d];
    for (int p0 = 0; p0 < cntE; p0 += 32) {
        int   src_l = 0;
        float dv_l  = 0.f;
        if (p0 + lane < cntE) { src_l = d_csr[start + p0 + lane]; dv_l = d_dinv[src_l]; }
        int lim = min(32, cntE - p0);
        for (int j = 0; j < lim; j++) {
            int   src = __shfl_sync(0xffffffffu, src_l, j);
            float dv  = __shfl_sync(0xffffffffu, dv_l, j);
            float2 v = *(const float2*)&d_o2[src * 64 + lane * 2];
            acc.x += v.x * dv; acc.y += v.y * dv;
        }
    }
    float2 o;
    o.x = acc.x * did;
    o.y = acc.y * did;
    *(float2*)&d_ag2[d * 64 + lane * 2] = o;
}

// ---------------- GEMM2 + bias + lrelu + pool: (agg2 @ W3) fused --------------
__global__ void k_gemm2pool(const float* __restrict__ W3, const float* __restrict__ b3,
                            const int* __restrict__ batch) {
    __shared__ float Ws[64 * 128];                 // [k][o]
    for (int i = threadIdx.x; i < 64 * 128; i += 256) Ws[i] = W3[i];
    __syncthreads();
    int q = threadIdx.x & 31;                      // output quad (128 outputs)
    int nl = threadIdx.x >> 5;                     // 8 nodes per block-iter
    for (int n0 = blockIdx.x * 8; n0 < NN; n0 += gridDim.x * 8) {
        int node = n0 + nl;                        // NN % 8 == 0
        const float4* g4 = (const float4*)&d_ag2[node * 64];
        float4 acc = *(const float4*)&b3[q * 4];
        #pragma unroll
        for (int kk = 0; kk < 16; kk++) {
            float4 gv = g4[kk];
            float4 w0 = *(const float4*)&Ws[(kk * 4 + 0) * 128 + q * 4];
            float4 w1 = *(const float4*)&Ws[(kk * 4 + 1) * 128 + q * 4];
            float4 w2 = *(const float4*)&Ws[(kk * 4 + 2) * 128 + q * 4];
            float4 w3 = *(const float4*)&Ws[(kk * 4 + 3) * 128 + q * 4];
            acc.x += gv.x * w0.x + gv.y * w1.x + gv.z * w2.x + gv.w * w3.x;
            acc.y += gv.x * w0.y + gv.y * w1.y + gv.z * w2.y + gv.w * w3.y;
            acc.z += gv.x * w0.z + gv.y * w1.z + gv.z * w2.z + gv.w * w3.z;
            acc.w += gv.x * w0.w + gv.y * w1.w + gv.z * w2.w + gv.w * w3.w;
        }
        int b = batch[node];
        redAdd4(&d_pool[b * 128 + q * 4],
                lrelu(acc.x, 0.01f), lrelu(acc.y, 0.01f),
                lrelu(acc.z, 0.01f), lrelu(acc.w, 0.01f));
    }
}

// ---------------- sequence branch ---------------------------------------------
__global__ void k_seq1(const float* __restrict__ seq, const float* __restrict__ w,
                       const float* __restrict__ bias,
                       const float* __restrict__ g, const float* __restrict__ be,
                       const float* __restrict__ m, const float* __restrict__ v) {
    int idx = blockIdx.x * 256 + threadIdx.x;       // BB*64*18
    int b = idx / 1152, r = idx % 1152, co = r / 18, t = r % 18;
    float acc = bias[co];
    #pragma unroll 5
    for (int ci = 0; ci < 30; ci++) {
        const float* sp = &seq[b * 600 + ci * 20 + t];
        const float* wp = &w[(co * 30 + ci) * 3];
        acc += sp[0] * wp[0] + sp[1] * wp[1] + sp[2] * wp[2];
    }
    acc = (acc - m[co]) * rsqrtf(v[co] + 1e-5f) * g[co] + be[co];
    d_s1[idx] = lrelu(acc, 0.01f);
}

__global__ void k_seq2(const float* __restrict__ w, const float* __restrict__ bias,
                       const float* __restrict__ g, const float* __restrict__ be,
                       const float* __restrict__ m, const float* __restrict__ v) {
    int idx = blockIdx.x * 256 + threadIdx.x;       // BB*64*16
    int b = idx >> 10, r = idx & 1023, co = r >> 4, t = r & 15;
    float acc = bias[co];
    #pragma unroll 8
    for (int ci = 0; ci < 64; ci++) {
        const float* sp = &d_s1[b * 1152 + ci * 18 + t];
        const float* wp = &w[(co * 64 + ci) * 3];
        acc += sp[0] * wp[0] + sp[1] * wp[1] + sp[2] * wp[2];
    }
    acc = (acc - m[co]) * rsqrtf(v[co] + 1e-5f) * g[co] + be[co];
    d_s2[idx] = lrelu(acc, 0.01f);
}

__global__ void k_fc1(const float* __restrict__ W, const float* __restrict__ bias) {
    int tid = threadIdx.x;                          // grid 64 x 256
    int o = tid & 63, q = tid >> 6;
    int b0 = blockIdx.x * 16 + q * 4;
    float a0 = bias[o], a1 = a0, a2 = a0, a3 = a0;
    #pragma unroll 4
    for (int k = 0; k < 1024; k++) {
        float ww = W[k * 64 + o];
        a0 += d_s2[(b0 + 0) * 1024 + k] * ww;
        a1 += d_s2[(b0 + 1) * 1024 + k] * ww;
        a2 += d_s2[(b0 + 2) * 1024 + k] * ww;
        a3 += d_s2[(b0 + 3) * 1024 + k] * ww;
    }
    d_fc[(b0 + 0) * 64 + o] = a0;
    d_fc[(b0 + 1) * 64 + o] = a1;
    d_fc[(b0 + 2) * 64 + o] = a2;
    d_fc[(b0 + 3) * 64 + o] = a3;
}

// ---------------- fusion + classifier head ------------------------------------
__global__ void k_head(const float* __restrict__ fusW, const float* __restrict__ fusb,
                       const float* __restrict__ c1W, const float* __restrict__ c1b,
                       const float* __restrict__ c3W, const float* __restrict__ c3b,
                       float* __restrict__ out) {
    __shared__ float comb[192], t1[128], t2[64];
    int b = blockIdx.x, tid = threadIdx.x;          // 128 threads
    if (tid < 128) comb[tid] = d_pool[b * 128 + tid] / fmaxf(d_cnt[b], 1.0f);
    if (tid < 64)  comb[128 + tid] = d_fc[b * 64 + tid];
    __syncthreads();
    float acc = fusb[tid];
    #pragma unroll 8
    for (int k = 0; k < 192; k++) acc += comb[k] * fusW[k * 128 + tid];
    t1[tid] = lrelu(acc, 0.01f);
    __syncthreads();
    if (tid < 64) {
        float a = c1b[tid];
        #pragma unroll 8
        for (int k = 0; k < 128; k++) a += t1[k] * c1W[k * 64 + tid];
        t2[tid] = lrelu(a, 0.01f);
    }
    __syncthreads();
    if (tid == 0) {
        float a = c3b[0];
        #pragma unroll 8
        for (int k = 0; k < 64; k++) a += t2[k] * c3W[k];
        out[b] = a;
    }
}

// ---------------- launch ------------------------------------------------------
extern "C" void kernel_launch(void* const* d_in, const int* in_sizes, int n_in,
                              void* d_out, int out_size) {
    const float* x     = (const float*)d_in[0];
    const int*   ei    = (const int*)  d_in[1];
    const int*   batch = (const int*)  d_in[2];
    const float* seq   = (const float*)d_in[3];
    const float* Wg    = (const float*)d_in[4];
    const float* atts  = (const float*)d_in[5];
    const float* attd  = (const float*)d_in[6];
    const float* bg    = (const float*)d_in[7];
    const float* W2    = (const float*)d_in[8];
    const float* b2    = (const float*)d_in[9];
    const float* W3    = (const float*)d_in[10];
    const float* b3    = (const float*)d_in[11];
    const float* c1w   = (const float*)d_in[12];
    const float* c1bv  = (const float*)d_in[13];
    const float* c2w   = (const float*)d_in[14];
    const float* c2bv  = (const float*)d_in[15];
    const float* bn1g  = (const float*)d_in[16];
    const float* bn1b  = (const float*)d_in[17];
    const float* bn1m  = (const float*)d_in[18];
    const float* bn1v  = (const float*)d_in[19];
    const float* bn2g  = (const float*)d_in[20];
    const float* bn2b  = (const float*)d_in[21];
    const float* bn2m  = (const float*)d_in[22];
    const float* bn2v  = (const float*)d_in[23];
    const float* fcW   = (const float*)d_in[24];
    const float* fcb   = (const float*)d_in[25];
    const float* fusW  = (const float*)d_in[26];
    const float* fusb  = (const float*)d_in[27];
    const float* cls1W = (const float*)d_in[28];
    const float* cls1b = (const float*)d_in[29];
    const float* cls3W = (const float*)d_in[30];
    const float* cls3b = (const float*)d_in[31];
    float* out = (float*)d_out;

    k_init  <<<512, 256>>>();
    k_att   <<<1, 64>>>(Wg, atts, attd);
    k_node2 <<<(NN + 255) / 256, 256>>>(x);
    k_hist  <<<(EE + 255) / 256, 256>>>(ei, batch);
    k_scanA <<<SCAN_B, 1024>>>();
    k_scanB <<<1, 128>>>();
    k_scanC <<<SCAN_B, 1024>>>();
    k_fill  <<<(EE + 255) / 256, 256>>>(ei);
    k_gat   <<<12500, 256>>>(Wg, bg);
    k_gemm1 <<<1184, 256>>>(W2);
    k_gcn1  <<<12500, 256>>>(b2);
    k_gcn2agg<<<12500, 256>>>();
    k_gemm2pool<<<1184, 256>>>(W3, b3, batch);
    k_seq1  <<<BB * 1152 / 256, 256>>>(seq, c1w, c1bv, bn1g, bn1b, bn1m, bn1v);
    k_seq2  <<<BB * 1024 / 256, 256>>>(c2w, c2bv, bn2g, bn2b, bn2m, bn2v);
    k_fc1   <<<64, 256>>>(fcW, fcb);
    k_head  <<<BB, 128>>>(fusW, fusb, cls1W, cls1b, cls3W, cls3b, out);
}

// round 9
// speedup vs baseline: 1.4990x; 1.2827x over previous
#include <cuda_runtime.h>

#define NN 100000
#define EE 1600000
#define BB 1024
#define SCAN_B 98   // ceil(NN/1024)

// ---------------- scratch (device globals) -----------------------------------
__device__ __align__(128) float d_x12 [NN * 12];   // x padded to 12 floats/row
__device__ __align__(128) float d_as  [NN * 4];
__device__ __align__(128) float d_ad  [NN * 4];
__device__ __align__(128) float d_gat [NN * 128];
__device__ __align__(128) float d_h1  [NN * 64];
__device__ __align__(128) float d_o2  [NN * 64];
__device__ __align__(128) float d_ag2 [NN * 64];   // aggregated o2 (pre-GEMM2)
__device__ __align__(128) float d_dinv[NN];
__device__ __align__(128) float d_pool[BB * 128];
__device__ __align__(128) float d_cnt [BB];
__device__ __align__(128) float d_s1  [BB * 64 * 18];
__device__ __align__(128) float d_s2  [BB * 64 * 16];
__device__ __align__(128) float d_fc  [BB * 64];
__device__ __align__(128) int   d_degi[NN];
__device__ __align__(128) int   d_off [NN];
__device__ __align__(128) int   d_cur [NN];
__device__ __align__(128) int   d_csr [EE];
__device__ __align__(128) int   d_bsum [SCAN_B];
__device__ __align__(128) int   d_bbase[SCAN_B];

__device__ __forceinline__ float lrelu(float x, float s) { return x < 0.f ? s * x : x; }

__device__ __forceinline__ void redAdd4(float* p, float a, float b, float c, float d) {
    asm volatile("red.global.add.v4.f32 [%0], {%1,%2,%3,%4};"
                 :: "l"(p), "f"(a), "f"(b), "f"(c), "f"(d) : "memory");
}

// ---------------- init --------------------------------------------------------
__global__ void k_init() {
    int i = blockIdx.x * 256 + threadIdx.x;
    if (i < NN)       d_degi[i] = 0;
    if (i < BB * 128) d_pool[i] = 0.f;
    if (i < BB)       d_cnt[i]  = 0.f;
}

// ---------------- per-node attn logits + padded x (att vectors fused) ---------
__global__ void k_node2(const float* __restrict__ x, const float* __restrict__ Wg,
                        const float* __restrict__ atts, const float* __restrict__ attd) {
    __shared__ float svs[36], svd[36];
    if (threadIdx.x < 36) {
        int h = threadIdx.x / 9, k = threadIdx.x % 9;
        float s = 0.f, d = 0.f;
        #pragma unroll
        for (int c = 0; c < 32; c++) {
            float w = Wg[k * 128 + h * 32 + c];
            s += w * atts[h * 32 + c];
            d += w * attd[h * 32 + c];
        }
        svs[threadIdx.x] = s;
        svd[threadIdx.x] = d;
    }
    __syncthreads();
    int n = blockIdx.x * 256 + threadIdx.x;
    if (n >= NN) return;
    float xv[9];
    #pragma unroll
    for (int k = 0; k < 9; k++) xv[k] = x[n * 9 + k];
    #pragma unroll
    for (int k = 0; k < 9; k++) d_x12[n * 12 + k] = xv[k];
    #pragma unroll
    for (int k = 9; k < 12; k++) d_x12[n * 12 + k] = 0.f;
    #pragma unroll
    for (int h = 0; h < 4; h++) {
        float as = 0.f, ad = 0.f;
        #pragma unroll
        for (int k = 0; k < 9; k++) {
            as += xv[k] * svs[h * 9 + k];
            ad += xv[k] * svd[h * 9 + k];
        }
        d_as[n * 4 + h] = as;
        d_ad[n * 4 + h] = ad;
    }
}

// ---------------- degree histogram + batch counts ------------------------------
__global__ void k_hist(const int* __restrict__ ei, const int* __restrict__ batch) {
    int idx = blockIdx.x * 256 + threadIdx.x;
    if (idx < EE) atomicAdd(&d_degi[ei[EE + idx]], 1);
    if (idx < NN) atomicAdd(&d_cnt[batch[idx]], 1.0f);
}

// ---------------- scan ---------------------------------------------------------
__global__ void k_scanA() {
    __shared__ int sm[1024];
    int i = blockIdx.x * 1024 + threadIdx.x;
    int v = (i < NN) ? d_degi[i] : 0;
    sm[threadIdx.x] = v;
    __syncthreads();
    for (int off = 1; off < 1024; off <<= 1) {
        int t = (threadIdx.x >= off) ? sm[threadIdx.x - off] : 0;
        __syncthreads();
        sm[threadIdx.x] += t;
        __syncthreads();
    }
    if (i < NN) d_off[i] = sm[threadIdx.x] - v;
    if (threadIdx.x == 1023) d_bsum[blockIdx.x] = sm[1023];
}

__global__ void k_scanB() {
    __shared__ int sm[128];
    int t = threadIdx.x;
    int v = (t < SCAN_B) ? d_bsum[t] : 0;
    sm[t] = v;
    __syncthreads();
    for (int off = 1; off < 128; off <<= 1) {
        int tv = (t >= off) ? sm[t - off] : 0;
        __syncthreads();
        sm[t] += tv;
        __syncthreads();
    }
    if (t < SCAN_B) d_bbase[t] = sm[t] - v;   // exclusive
}

__global__ void k_scanC() {
    int i = blockIdx.x * 1024 + threadIdx.x;
    if (i < NN) {
        int o = d_off[i] + d_bbase[blockIdx.x];
        d_off[i] = o;
        d_cur[i] = o;
        d_dinv[i] = rsqrtf((float)(d_degi[i] + 1));
    }
}

// ---------------- CSR fill ------------------------------------------------------
__global__ void k_fill(const int* __restrict__ ei) {
    int idx = blockIdx.x * 256 + threadIdx.x;
    if (idx < EE) {
        int dst = ei[EE + idx];
        int p = atomicAdd(&d_cur[dst], 1);
        d_csr[p] = ei[idx];
    }
}

// ---------------- fused GAT on hoisted x: warp/node, lane=(slot,head) ---------
__global__ void k_gat(const float* __restrict__ Wg, const float* __restrict__ bg) {
    __shared__ float sm_ax[8][4][10];
    int wb = threadIdx.x >> 5;
    int node = blockIdx.x * 8 + wb;
    if (node >= NN) return;
    int lane = threadIdx.x & 31;
    int g = lane >> 2;          // neighbor slot 0..7
    int h = lane & 3;           // head

    float add_ = d_ad[node * 4 + h];
    float m = -1e30f, s = 0.f;
    float ax[12];
    #pragma unroll
    for (int k = 0; k < 12; k++) ax[k] = 0.f;

    int start = d_off[node], cnt = d_degi[node];
    for (int p0 = 0; p0 < cnt; p0 += 8) {
        int idx = p0 + g;
        if (idx < cnt) {
            int src = d_csr[start + idx];
            float e = lrelu(d_as[src * 4 + h] + add_, 0.2f);
            float nm = fmaxf(m, e);
            float r = __expf(m - nm);
            float w = __expf(e - nm);
            s = s * r + w;
            const float4* xr = (const float4*)&d_x12[src * 12];
            float4 x0 = xr[0], x1 = xr[1], x2 = xr[2];
            ax[0] = ax[0] * r + w * x0.x;  ax[1] = ax[1] * r + w * x0.y;
            ax[2] = ax[2] * r + w * x0.z;  ax[3] = ax[3] * r + w * x0.w;
            ax[4] = ax[4] * r + w * x1.x;  ax[5] = ax[5] * r + w * x1.y;
            ax[6] = ax[6] * r + w * x1.z;  ax[7] = ax[7] * r + w * x1.w;
            ax[8] = ax[8] * r + w * x2.x;
            m = nm;
        }
    }
    #pragma unroll
    for (int off = 4; off < 32; off <<= 1) {
        float m2 = __shfl_xor_sync(0xffffffffu, m, off);
        float s2 = __shfl_xor_sync(0xffffffffu, s, off);
        float nm = fmaxf(m, m2);
        float r1 = __expf(m - nm);
        float r2 = __expf(m2 - nm);
        s = s * r1 + s2 * r2;
        #pragma unroll
        for (int k = 0; k < 9; k++) {
            float a2 = __shfl_xor_sync(0xffffffffu, ax[k], off);
            ax[k] = ax[k] * r1 + a2 * r2;
        }
        m = nm;
    }
    if (lane < 4) {
        float es = lrelu(d_as[node * 4 + lane] + add_, 0.2f);
        float nm = fmaxf(m, es);
        float r = __expf(m - nm);
        float wse = __expf(es - nm);
        float st = s * r + wse;
        float inv = 1.f / (st + 1e-16f);
        #pragma unroll
        for (int k = 0; k < 9; k++)
            sm_ax[wb][lane][k] = (ax[k] * r + wse * d_x12[node * 12 + k]) * inv;
    }
    __syncwarp();
    int hh = lane >> 3;
    float a[9];
    #pragma unroll
    for (int k = 0; k < 9; k++) a[k] = sm_ax[wb][hh][k];
    float4 o = *(const float4*)&bg[lane * 4];
    #pragma unroll
    for (int k = 0; k < 9; k++) {
        float4 wr = *(const float4*)&Wg[k * 128 + lane * 4];
        o.x += a[k] * wr.x; o.y += a[k] * wr.y;
        o.z += a[k] * wr.z; o.w += a[k] * wr.w;
    }
    o.x = lrelu(o.x, 0.01f); o.y = lrelu(o.y, 0.01f);
    o.z = lrelu(o.z, 0.01f); o.w = lrelu(o.w, 0.01f);
    *(float4*)&d_gat[node * 128 + lane * 4] = o;
}

// ---------------- GEMM1: h1 = d_gat @ W2 (128 -> 64), 4 nodes/thread ----------
__global__ void k_gemm1(const float* __restrict__ W2) {
    __shared__ float Ws[128 * 64];                 // [k][o]
    for (int i = threadIdx.x; i < 128 * 64; i += 256) Ws[i] = W2[i];
    __syncthreads();
    int q = threadIdx.x & 15;                      // output quad (64 outputs)
    int nl = threadIdx.x >> 4;                     // 0..15
    for (int n0 = blockIdx.x * 64; n0 < NN; n0 += gridDim.x * 64) {
        int nb = n0 + nl * 4;
        int m0 = min(nb + 0, NN - 1), m1 = min(nb + 1, NN - 1);
        int m2 = min(nb + 2, NN - 1), m3 = min(nb + 3, NN - 1);
        const float4* gA = (const float4*)&d_gat[m0 * 128];
        const float4* gB = (const float4*)&d_gat[m1 * 128];
        const float4* gC = (const float4*)&d_gat[m2 * 128];
        const float4* gD = (const float4*)&d_gat[m3 * 128];
        float4 aA = make_float4(0.f,0.f,0.f,0.f), aB = aA, aC = aA, aD = aA;
        #pragma unroll
        for (int kk = 0; kk < 32; kk++) {
            float4 w0 = *(const float4*)&Ws[(kk * 4 + 0) * 64 + q * 4];
            float4 w1 = *(const float4*)&Ws[(kk * 4 + 1) * 64 + q * 4];
            float4 w2 = *(const float4*)&Ws[(kk * 4 + 2) * 64 + q * 4];
            float4 w3 = *(const float4*)&Ws[(kk * 4 + 3) * 64 + q * 4];
            float4 v;
            v = gA[kk];
            aA.x += v.x*w0.x + v.y*w1.x + v.z*w2.x + v.w*w3.x;
            aA.y += v.x*w0.y + v.y*w1.y + v.z*w2.y + v.w*w3.y;
            aA.z += v.x*w0.z + v.y*w1.z + v.z*w2.z + v.w*w3.z;
            aA.w += v.x*w0.w + v.y*w1.w + v.z*w2.w + v.w*w3.w;
            v = gB[kk];
            aB.x += v.x*w0.x + v.y*w1.x + v.z*w2.x + v.w*w3.x;
            aB.y += v.x*w0.y + v.y*w1.y + v.z*w2.y + v.w*w3.y;
            aB.z += v.x*w0.z + v.y*w1.z + v.z*w2.z + v.w*w3.z;
            aB.w += v.x*w0.w + v.y*w1.w + v.z*w2.w + v.w*w3.w;
            v = gC[kk];
            aC.x += v.x*w0.x + v.y*w1.x + v.z*w2.x + v.w*w3.x;
            aC.y += v.x*w0.y + v.y*w1.y + v.z*w2.y + v.w*w3.y;
            aC.z += v.x*w0.z + v.y*w1.z + v.z*w2.z + v.w*w3.z;
            aC.w += v.x*w0.w + v.y*w1.w + v.z*w2.w + v.w*w3.w;
            v = gD[kk];
            aD.x += v.x*w0.x + v.y*w1.x + v.z*w2.x + v.w*w3.x;
            aD.y += v.x*w0.y + v.y*w1.y + v.z*w2.y + v.w*w3.y;
            aD.z += v.x*w0.z + v.y*w1.z + v.z*w2.z + v.w*w3.z;
            aD.w += v.x*w0.w + v.y*w1.w + v.z*w2.w + v.w*w3.w;
        }
        if (nb + 0 < NN) *(float4*)&d_h1[(nb + 0) * 64 + q * 4] = aA;
        if (nb + 1 < NN) *(float4*)&d_h1[(nb + 1) * 64 + q * 4] = aB;
        if (nb + 2 < NN) *(float4*)&d_h1[(nb + 2) * 64 + q * 4] = aC;
        if (nb + 3 < NN) *(float4*)&d_h1[(nb + 3) * 64 + q * 4] = aD;
    }
}

// ---------------- GCN1 gather (warp per node) — unchanged ---------------------
__global__ void k_gcn1(const float* __restrict__ b2) {
    int gw = (blockIdx.x * 256 + threadIdx.x) >> 5;
    if (gw >= NN) return;
    int lane = threadIdx.x & 31;
    int d = gw;
    float did = d_dinv[d];

    float2 hv = *(const float2*)&d_h1[d * 64 + lane * 2];
    float2 acc; acc.x = hv.x * did; acc.y = hv.y * did;

    int start = d_off[d];
    int cntE  = d_degi[d];
    for (int p0 = 0; p0 < cntE; p0 += 32) {
        int   src_l = 0;
        float dv_l  = 0.f;
        if (p0 + lane < cntE) { src_l = d_csr[start + p0 + lane]; dv_l = d_dinv[src_l]; }
        int lim = min(32, cntE - p0);
        for (int j = 0; j < lim; j++) {
            int   src = __shfl_sync(0xffffffffu, src_l, j);
            float dv  = __shfl_sync(0xffffffffu, dv_l, j);
            float2 v = *(const float2*)&d_h1[src * 64 + lane * 2];
            acc.x += v.x * dv; acc.y += v.y * dv;
        }
    }
    float2 o;
    o.x = lrelu(acc.x * did + b2[lane * 2 + 0], 0.01f);
    o.y = lrelu(acc.y * did + b2[lane * 2 + 1], 0.01f);
    *(float2*)&d_o2[d * 64 + lane * 2] = o;
}

// ---------------- GCN2 aggregation on o2 — unchanged --------------------------
__global__ void k_gcn2agg() {
    int gw = (blockIdx.x * 256 + threadIdx.x) >> 5;
    if (gw >= NN) return;
    int lane = threadIdx.x & 31;
    int d = gw;
    float did = d_dinv[d];

    float2 hv = *(const float2*)&d_o2[d * 64 + lane * 2];
    float2 acc; acc.x = hv.x * did; acc.y = hv.y * did;

    int start = d_off[d];
    int cntE  = d_degi[d];
    for (int p0 = 0; p0 < cntE; p0 += 32) {
        int   src_l = 0;
        float dv_l  = 0.f;
        if (p0 + lane < cntE) { src_l = d_csr[start + p0 + lane]; dv_l = d_dinv[src_l]; }
        int lim = min(32, cntE - p0);
        for (int j = 0; j < lim; j++) {
            int   src = __shfl_sync(0xffffffffu, src_l, j);
            float dv  = __shfl_sync(0xffffffffu, dv_l, j);
            float2 v = *(const float2*)&d_o2[src * 64 + lane * 2];
            acc.x += v.x * dv; acc.y += v.y * dv;
        }
    }
    float2 o;
    o.x = acc.x * did;
    o.y = acc.y * did;
    *(float2*)&d_ag2[d * 64 + lane * 2] = o;
}

// ---------------- GEMM2 + bias + lrelu + pool, 4 nodes/thread -----------------
__global__ void k_gemm2pool(const float* __restrict__ W3, const float* __restrict__ b3,
                            const int* __restrict__ batch) {
    __shared__ float Ws[64 * 128];                 // [k][o]
    for (int i = threadIdx.x; i < 64 * 128; i += 256) Ws[i] = W3[i];
    __syncthreads();
    int q = threadIdx.x & 31;                      // output quad (128 outputs)
    int nl = threadIdx.x >> 5;                     // 0..7
    float4 bb = *(const float4*)&b3[q * 4];
    for (int n0 = blockIdx.x * 32; n0 < NN; n0 += gridDim.x * 32) {
        int nb = n0 + nl * 4;                      // NN % 32 == 0 -> no tail
        const float4* gA = (const float4*)&d_ag2[(nb + 0) * 64];
        const float4* gB = (const float4*)&d_ag2[(nb + 1) * 64];
        const float4* gC = (const float4*)&d_ag2[(nb + 2) * 64];
        const float4* gD = (const float4*)&d_ag2[(nb + 3) * 64];
        float4 aA = bb, aB = bb, aC = bb, aD = bb;
        #pragma unroll
        for (int kk = 0; kk < 16; kk++) {
            float4 w0 = *(const float4*)&Ws[(kk * 4 + 0) * 128 + q * 4];
            float4 w1 = *(const float4*)&Ws[(kk * 4 + 1) * 128 + q * 4];
            float4 w2 = *(const float4*)&Ws[(kk * 4 + 2) * 128 + q * 4];
            float4 w3 = *(const float4*)&Ws[(kk * 4 + 3) * 128 + q * 4];
            float4 v;
            v = gA[kk];
            aA.x += v.x*w0.x + v.y*w1.x + v.z*w2.x + v.w*w3.x;
            aA.y += v.x*w0.y + v.y*w1.y + v.z*w2.y + v.w*w3.y;
            aA.z += v.x*w0.z + v.y*w1.z + v.z*w2.z + v.w*w3.z;
            aA.w += v.x*w0.w + v.y*w1.w + v.z*w2.w + v.w*w3.w;
            v = gB[kk];
            aB.x += v.x*w0.x + v.y*w1.x + v.z*w2.x + v.w*w3.x;
            aB.y += v.x*w0.y + v.y*w1.y + v.z*w2.y + v.w*w3.y;
            aB.z += v.x*w0.z + v.y*w1.z + v.z*w2.z + v.w*w3.z;
            aB.w += v.x*w0.w + v.y*w1.w + v.z*w2.w + v.w*w3.w;
            v = gC[kk];
            aC.x += v.x*w0.x + v.y*w1.x + v.z*w2.x + v.w*w3.x;
            aC.y += v.x*w0.y + v.y*w1.y + v.z*w2.y + v.w*w3.y;
            aC.z += v.x*w0.z + v.y*w1.z + v.z*w2.z + v.w*w3.z;
            aC.w += v.x*w0.w + v.y*w1.w + v.z*w2.w + v.w*w3.w;
            v = gD[kk];
            aD.x += v.x*w0.x + v.y*w1.x + v.z*w2.x + v.w*w3.x;
            aD.y += v.x*w0.y + v.y*w1.y + v.z*w2.y + v.w*w3.y;
            aD.z += v.x*w0.z + v.y*w1.z + v.z*w2.z + v.w*w3.z;
            aD.w += v.x*w0.w + v.y*w1.w + v.z*w2.w + v.w*w3.w;
        }
        int b0 = batch[nb + 0], b1 = batch[nb + 1];
        int b2i = batch[nb + 2], b3i = batch[nb + 3];
        redAdd4(&d_pool[b0 * 128 + q * 4],
                lrelu(aA.x,0.01f), lrelu(aA.y,0.01f), lrelu(aA.z,0.01f), lrelu(aA.w,0.01f));
        redAdd4(&d_pool[b1 * 128 + q * 4],
                lrelu(aB.x,0.01f), lrelu(aB.y,0.01f), lrelu(aB.z,0.01f), lrelu(aB.w,0.01f));
        redAdd4(&d_pool[b2i * 128 + q * 4],
                lrelu(aC.x,0.01f), lrelu(aC.y,0.01f), lrelu(aC.z,0.01f), lrelu(aC.w,0.01f));
        redAdd4(&d_pool[b3i * 128 + q * 4],
                lrelu(aD.x,0.01f), lrelu(aD.y,0.01f), lrelu(aD.z,0.01f), lrelu(aD.w,0.01f));
    }
}

// ---------------- sequence branch ---------------------------------------------
__global__ void k_seq1(const float* __restrict__ seq, const float* __restrict__ w,
                       const float* __restrict__ bias,
                       const float* __restrict__ g, const float* __restrict__ be,
                       const float* __restrict__ m, const float* __restrict__ v) {
    int idx = blockIdx.x * 256 + threadIdx.x;       // BB*64*18
    int b = idx / 1152, r = idx % 1152, co = r / 18, t = r % 18;
    float acc = bias[co];
    #pragma unroll 5
    for (int ci = 0; ci < 30; ci++) {
        const float* sp = &seq[b * 600 + ci * 20 + t];
        const float* wp = &w[(co * 30 + ci) * 3];
        acc += sp[0] * wp[0] + sp[1] * wp[1] + sp[2] * wp[2];
    }
    acc = (acc - m[co]) * rsqrtf(v[co] + 1e-5f) * g[co] + be[co];
    d_s1[idx] = lrelu(acc, 0.01f);
}

__global__ void k_seq2(const float* __restrict__ w, const float* __restrict__ bias,
                       const float* __restrict__ g, const float* __restrict__ be,
                       const float* __restrict__ m, const float* __restrict__ v) {
    int idx = blockIdx.x * 256 + threadIdx.x;       // BB*64*16
    int b = idx >> 10, r = idx & 1023, co = r >> 4, t = r & 15;
    float acc = bias[co];
    #pragma unroll 8
    for (int ci = 0; ci < 64; ci++) {
        const float* sp = &d_s1[b * 1152 + ci * 18 + t];
        const float* wp = &w[(co * 64 + ci) * 3];
        acc += sp[0] * wp[0] + sp[1] * wp[1] + sp[2] * wp[2];
    }
    acc = (acc - m[co]) * rsqrtf(v[co] + 1e-5f) * g[co] + be[co];
    d_s2[idx] = lrelu(acc, 0.01f);
}

__global__ void k_fc1(const float* __restrict__ W, const float* __restrict__ bias) {
    int tid = threadIdx.x;                          // grid 64 x 256
    int o = tid & 63, q = tid >> 6;
    int b0 = blockIdx.x * 16 + q * 4;
    float a0 = bias[o], a1 = a0, a2 = a0, a3 = a0;
    #pragma unroll 4
    for (int k = 0; k < 1024; k++) {
        float ww = W[k * 64 + o];
        a0 += d_s2[(b0 + 0) * 1024 + k] * ww;
        a1 += d_s2[(b0 + 1) * 1024 + k] * ww;
        a2 += d_s2[(b0 + 2) * 1024 + k] * ww;
        a3 += d_s2[(b0 + 3) * 1024 + k] * ww;
    }
    d_fc[(b0 + 0) * 64 + o] = a0;
    d_fc[(b0 + 1) * 64 + o] = a1;
    d_fc[(b0 + 2) * 64 + o] = a2;
    d_fc[(b0 + 3) * 64 + o] = a3;
}

// ---------------- fusion + classifier head ------------------------------------
__global__ void k_head(const float* __restrict__ fusW, const float* __restrict__ fusb,
                       const float* __restrict__ c1W, const float* __restrict__ c1b,
                       const float* __restrict__ c3W, const float* __restrict__ c3b,
                       float* __restrict__ out) {
    __shared__ float comb[192], t1[128], t2[64];
    int b = blockIdx.x, tid = threadIdx.x;          // 128 threads
    if (tid < 128) comb[tid] = d_pool[b * 128 + tid] / fmaxf(d_cnt[b], 1.0f);
    if (tid < 64)  comb[128 + tid] = d_fc[b * 64 + tid];
    __syncthreads();
    float acc = fusb[tid];
    #pragma unroll 8
    for (int k = 0; k < 192; k++) acc += comb[k] * fusW[k * 128 + tid];
    t1[tid] = lrelu(acc, 0.01f);
    __syncthreads();
    if (tid < 64) {
        float a = c1b[tid];
        #pragma unroll 8
        for (int k = 0; k < 128; k++) a += t1[k] * c1W[k * 64 + tid];
        t2[tid] = lrelu(a, 0.01f);
    }
    __syncthreads();
    if (tid == 0) {
        float a = c3b[0];
        #pragma unroll 8
        for (int k = 0; k < 64; k++) a += t2[k] * c3W[k];
        out[b] = a;
    }
}

// ---------------- launch ------------------------------------------------------
extern "C" void kernel_launch(void* const* d_in, const int* in_sizes, int n_in,
                              void* d_out, int out_size) {
    const float* x     = (const float*)d_in[0];
    const int*   ei    = (const int*)  d_in[1];
    const int*   batch = (const int*)  d_in[2];
    const float* seq   = (const float*)d_in[3];
    const float* Wg    = (const float*)d_in[4];
    const float* atts  = (const float*)d_in[5];
    const float* attd  = (const float*)d_in[6];
    const float* bg    = (const float*)d_in[7];
    const float* W2    = (const float*)d_in[8];
    const float* b2    = (const float*)d_in[9];
    const float* W3    = (const float*)d_in[10];
    const float* b3    = (const float*)d_in[11];
    const float* c1w   = (const float*)d_in[12];
    const float* c1bv  = (const float*)d_in[13];
    const float* c2w   = (const float*)d_in[14];
    const float* c2bv  = (const float*)d_in[15];
    const float* bn1g  = (const float*)d_in[16];
    const float* bn1b  = (const float*)d_in[17];
    const float* bn1m  = (const float*)d_in[18];
    const float* bn1v  = (const float*)d_in[19];
    const float* bn2g  = (const float*)d_in[20];
    const float* bn2b  = (const float*)d_in[21];
    const float* bn2m  = (const float*)d_in[22];
    const float* bn2v  = (const float*)d_in[23];
    const float* fcW   = (const float*)d_in[24];
    const float* fcb   = (const float*)d_in[25];
    const float* fusW  = (const float*)d_in[26];
    const float* fusb  = (const float*)d_in[27];
    const float* cls1W = (const float*)d_in[28];
    const float* cls1b = (const float*)d_in[29];
    const float* cls3W = (const float*)d_in[30];
    const float* cls3b = (const float*)d_in[31];
    float* out = (float*)d_out;

    k_init  <<<512, 256>>>();
    k_node2 <<<(NN + 255) / 256, 256>>>(x, Wg, atts, attd);
    k_hist  <<<(EE + 255) / 256, 256>>>(ei, batch);
    k_scanA <<<SCAN_B, 1024>>>();
    k_scanB <<<1, 128>>>();
    k_scanC <<<SCAN_B, 1024>>>();
    k_fill  <<<(EE + 255) / 256, 256>>>(ei);
    k_gat   <<<12500, 256>>>(Wg, bg);
    k_gemm1 <<<1563, 256>>>(W2);
    k_gcn1  <<<12500, 256>>>(b2);
    k_gcn2agg<<<12500, 256>>>();
    k_gemm2pool<<<3125, 256>>>(W3, b3, batch);
    k_seq1  <<<BB * 1152 / 256, 256>>>(seq, c1w, c1bv, bn1g, bn1b, bn1m, bn1v);
    k_seq2  <<<BB * 1024 / 256, 256>>>(c2w, c2bv, bn2g, bn2b, bn2m, bn2v);
    k_fc1   <<<64, 256>>>(fcW, fcb);
    k_head  <<<BB, 128>>>(fusW, fusb, cls1W, cls1b, cls3W, cls3b, out);
}